// round 13
// baseline (speedup 1.0000x reference)
#include <cuda_runtime.h>
#include <cuda_bf16.h>
#include <mma.h>

using namespace nvcuda;

#define BN     1024
#define NITER  50
#define EPS    0.05f
#define MMASS  0.95f
#define NB     32          // iteration blocks (32 rows + 32 cols each)
#define NTI    512         // threads per iteration block (16 warps)

// ---------------- static device scratch (no allocations allowed) ------------
__device__ __align__(16) float          g_M  [BN * BN];     // 4 MB
__device__ __align__(16) __nv_bfloat16  g_Abf[BN * BN];     // 2 MB
__device__ __align__(16) __nv_bfloat16  g_Tbf[BN * BN];     // 2 MB
__device__ __align__(16) __nv_bfloat16  g_K0 [BN * BN];     // 2 MB
__device__ __align__(16) __nv_bfloat16  g_K0T[BN * BN];     // 2 MB
__device__ __align__(16) float g_na[BN], g_nt[BN];
__device__ __align__(16) float g_maxp[128];
__device__ __align__(16) float g_sumpB[256];
__device__ __align__(16) float g_yp[NB * BN];               // [src][i]
__device__ __align__(16) float g_zp[NB * BN];               // [src][j]
__device__ __align__(16) float g_beta[BN];
__device__ __align__(16) float g_s2p[NB], g_lossp[NB];
__device__ unsigned g_flag[NB];                              // zero-init

// ---------------- warp helpers ---------------------------------------------
__device__ __forceinline__ float warp_sum(float v) {
    #pragma unroll
    for (int s = 16; s; s >>= 1) v += __shfl_xor_sync(0xffffffffu, v, s);
    return v;
}
__device__ __forceinline__ float warp_max(float v) {
    #pragma unroll
    for (int s = 16; s; s >>= 1) v = fmaxf(v, __shfl_xor_sync(0xffffffffu, v, s));
    return v;
}
__device__ __forceinline__ float red128_max(const float* p, int lane) {
    float s = fmaxf(fmaxf(__ldcg(p + lane), __ldcg(p + lane + 32)),
                    fmaxf(__ldcg(p + lane + 64), __ldcg(p + lane + 96)));
    return warp_max(s);
}

// -------- lean release/acquire flag barrier over NB blocks ------------------
// arrive: one __syncthreads, then tid0 does a release store (fence folded in).
// wait: EVERY warp polls all 32 flags with acquire loads; no block-wide sync.
__device__ __forceinline__ void bar_arrive(int b, int tid, unsigned eph) {
    __syncthreads();
    if (tid == 0)
        asm volatile("st.release.gpu.u32 [%0], %1;"
                     :: "l"(g_flag + b), "r"(eph) : "memory");
}
__device__ __forceinline__ void bar_wait(int lane, unsigned eph) {
    unsigned f;
    do {
        asm volatile("ld.acquire.gpu.u32 %0, [%1];"
                     : "=r"(f) : "l"(g_flag + lane) : "memory");
    } while (__any_sync(0xffffffffu, f < eph));
}

__device__ __forceinline__ float2 bf2u(unsigned u) {
    return __bfloat1622float2(*(const __nv_bfloat162*)&u);
}

// ===================== K1: fp32 -> bf16 + row norms =========================
__global__ void __launch_bounds__(256)
k_convert(const float* __restrict__ A, const float* __restrict__ T) {
    const int b = blockIdx.x, tid = threadIdx.x;
    const int w = tid >> 5, lane = tid & 31;
    const int idx = b * 8 + w;                       // 0..2047
    int row; const float* src; __nv_bfloat16* dst; float* ndst;
    if (idx < BN) { row = idx;      src = A + (size_t)row * BN; dst = g_Abf + (size_t)row * BN; ndst = g_na; }
    else          { row = idx - BN; src = T + (size_t)row * BN; dst = g_Tbf + (size_t)row * BN; ndst = g_nt; }
    const float4* s4 = (const float4*)src;
    __nv_bfloat162* d2 = (__nv_bfloat162*)dst;
    float nrm = 0.f;
    #pragma unroll
    for (int q = 0; q < 8; q++) {
        int c4 = q * 32 + lane;
        float4 v = s4[c4];
        nrm = fmaf(v.x, v.x, fmaf(v.y, v.y, fmaf(v.z, v.z, fmaf(v.w, v.w, nrm))));
        d2[c4 * 2]     = __floats2bfloat162_rn(v.x, v.y);
        d2[c4 * 2 + 1] = __floats2bfloat162_rn(v.z, v.w);
    }
    nrm = warp_sum(nrm);
    if (lane == 0) __stcg(&ndst[row], nrm);
}

// ===================== K2: GEMM -> M (fp32) + per-block max =================
#define DT_PITCH 68
__global__ void __launch_bounds__(256)
k_gemm() {
    __shared__ float dt[128 * DT_PITCH];
    __shared__ float s_warp[8];
    const int b = blockIdx.x, tid = threadIdx.x;
    const int w = tid >> 5, lane = tid & 31;
    const int tm = (b >> 4) * 128;
    const int tn = (b & 15) * 64;
    const int wm = w >> 1, wn = w & 1;

    wmma::fragment<wmma::accumulator, 16, 16, 16, float> c[2][2];
    #pragma unroll
    for (int mi = 0; mi < 2; mi++)
        #pragma unroll
        for (int ni = 0; ni < 2; ni++) wmma::fill_fragment(c[mi][ni], 0.f);

    #pragma unroll 1
    for (int k = 0; k < BN; k += 16) {
        wmma::fragment<wmma::matrix_a, 16, 16, 16, __nv_bfloat16, wmma::row_major> af[2];
        wmma::fragment<wmma::matrix_b, 16, 16, 16, __nv_bfloat16, wmma::col_major> bf[2];
        #pragma unroll
        for (int mi = 0; mi < 2; mi++)
            wmma::load_matrix_sync(af[mi], g_Abf + (size_t)(tm + wm * 32 + mi * 16) * BN + k, BN);
        #pragma unroll
        for (int ni = 0; ni < 2; ni++)
            wmma::load_matrix_sync(bf[ni], g_Tbf + (size_t)(tn + wn * 32 + ni * 16) * BN + k, BN);
        #pragma unroll
        for (int mi = 0; mi < 2; mi++)
            #pragma unroll
            for (int ni = 0; ni < 2; ni++)
                wmma::mma_sync(c[mi][ni], af[mi], bf[ni], c[mi][ni]);
    }
    #pragma unroll
    for (int mi = 0; mi < 2; mi++)
        #pragma unroll
        for (int ni = 0; ni < 2; ni++)
            wmma::store_matrix_sync(&dt[(wm * 32 + mi * 16) * DT_PITCH + wn * 32 + ni * 16],
                                    c[mi][ni], DT_PITCH, wmma::mem_row_major);
    __syncthreads();

    float lmax = 0.f;
    #pragma unroll 1
    for (int f = tid; f < 2048; f += 256) {
        int r = f >> 4, c4 = f & 15;
        float4 d = *(const float4*)&dt[r * DT_PITCH + c4 * 4];
        float  nai = __ldcg(&g_na[tm + r]);
        float4 nt4 = __ldcg(((const float4*)g_nt) + (tn >> 2) + c4);
        float4 mv;
        mv.x = fmaxf(nai + nt4.x - 2.f * d.x, 0.f);
        mv.y = fmaxf(nai + nt4.y - 2.f * d.y, 0.f);
        mv.z = fmaxf(nai + nt4.z - 2.f * d.z, 0.f);
        mv.w = fmaxf(nai + nt4.w - 2.f * d.w, 0.f);
        lmax = fmaxf(lmax, fmaxf(fmaxf(mv.x, mv.y), fmaxf(mv.z, mv.w)));
        __stcg(((float4*)(g_M + (size_t)(tm + r) * BN + tn)) + c4, mv);
    }
    lmax = warp_max(lmax);
    if (lane == 0) s_warp[w] = lmax;
    __syncthreads();
    if (tid == 0) {
        float mx = s_warp[0];
        #pragma unroll
        for (int k = 1; k < 8; k++) mx = fmaxf(mx, s_warp[k]);
        __stcg(&g_maxp[b], mx);
    }
}

// ===================== K3: build K0 (bf16) + K0^T + sum partials ============
#define ST_PITCH 66   // even pitch keeps bf162 smem stores 4B-aligned
__global__ void __launch_bounds__(256)
k_build() {
    __shared__ __nv_bfloat16 st[64 * ST_PITCH];
    __shared__ float s_warp[8];
    __shared__ float s_max;
    const int b = blockIdx.x, tid = threadIdx.x;
    const int w = tid >> 5, lane = tid & 31;
    const int ti = b >> 4, tj = b & 15;              // 64x64 tile

    if (w == 0) {
        float mx = red128_max(g_maxp, lane);
        if (lane == 0) s_max = mx;
    }
    __syncthreads();
    const float kscale = 1.0f / (s_max * EPS);

    float psum = 0.f;
    #pragma unroll
    for (int rr = 0; rr < 8; rr++) {
        int r = w * 8 + rr;
        size_t i = (size_t)(ti * 64 + r);
        float2 m = __ldcg(((const float2*)(g_M + i * BN + tj * 64)) + lane);
        float e0 = __expf(-m.x * kscale), e1 = __expf(-m.y * kscale);
        psum += e0 + e1;
        __nv_bfloat162 p = __floats2bfloat162_rn(e0, e1);
        ((__nv_bfloat162*)(g_K0 + i * BN + tj * 64))[lane] = p;
        *(__nv_bfloat162*)&st[r * ST_PITCH + 2 * lane] = p;
    }
    psum = warp_sum(psum);
    if (lane == 0) s_warp[w] = psum;
    __syncthreads();
    if (tid == 0) {
        float s = 0.f;
        #pragma unroll
        for (int k = 0; k < 8; k++) s += s_warp[k];
        __stcg(&g_sumpB[b], s);
    }
    #pragma unroll
    for (int cc = 0; cc < 8; cc++) {
        int c = w * 8 + cc;
        __nv_bfloat16 a0 = st[(2 * lane)     * ST_PITCH + c];
        __nv_bfloat16 a1 = st[(2 * lane + 1) * ST_PITCH + c];
        __nv_bfloat162 p; p.x = a0; p.y = a1;
        ((__nv_bfloat162*)(g_K0T + (size_t)(tj * 64 + c) * BN + ti * 64))[lane] = p;
    }
}

// ===================== K4: iteration kernel (32 x 512, register slabs) ======
__global__ void __launch_bounds__(NTI, 1)
k_iter(float* __restrict__ out) {
    extern __shared__ __align__(16) char smraw[];
    __nv_bfloat16* s_mat = (__nv_bfloat16*)smraw;        // 64 KB staging
    float* s_red = (float*)(smraw + 65536);              // 512 floats
    float* s_pii = s_red + 512;                          // 32 floats

    const int b = blockIdx.x, tid = threadIdx.x;
    const int w = tid >> 5, lane = tid & 31;
    unsigned eph = g_flag[b];                             // monotone across replays

    // ---- stage K0 rows (own 32) then pack into registers -------------------
    // k0p[q]    : rows (2q,2q+1) at column i1 = tid        (q = 0..15)
    // k0p[16+q] : rows (2q,2q+1) at column i2 = 512 + tid
    unsigned k0p[32], ktp[32];
    {
        const uint4* src = (const uint4*)(g_K0 + (size_t)b * 32 * BN);
        uint4* dst = (uint4*)s_mat;
        #pragma unroll
        for (int q = 0; q < 8; q++) dst[q * NTI + tid] = __ldcg(src + q * NTI + tid);
    }
    __syncthreads();
    #pragma unroll
    for (int q = 0; q < 16; q++) {
        __nv_bfloat162 p;
        p.x = s_mat[(2 * q) * BN + tid];       p.y = s_mat[(2 * q + 1) * BN + tid];
        k0p[q] = *(unsigned*)&p;
        p.x = s_mat[(2 * q) * BN + 512 + tid]; p.y = s_mat[(2 * q + 1) * BN + 512 + tid];
        k0p[16 + q] = *(unsigned*)&p;
    }
    __syncthreads();
    {
        const uint4* src = (const uint4*)(g_K0T + (size_t)b * 32 * BN);
        uint4* dst = (uint4*)s_mat;
        #pragma unroll
        for (int q = 0; q < 8; q++) dst[q * NTI + tid] = __ldcg(src + q * NTI + tid);
    }
    __syncthreads();
    #pragma unroll
    for (int q = 0; q < 16; q++) {
        __nv_bfloat162 p;
        p.x = s_mat[(2 * q) * BN + tid];       p.y = s_mat[(2 * q + 1) * BN + tid];
        ktp[q] = *(unsigned*)&p;
        p.x = s_mat[(2 * q) * BN + 512 + tid]; p.y = s_mat[(2 * q + 1) * BN + 512 + tid];
        ktp[16 + q] = *(unsigned*)&p;
    }

    // ---- warp-redundant scalar state: lane <-> row/col 32b+lane ------------
    float g;
    {
        float s = 0.f;
        #pragma unroll
        for (int q = 0; q < 8; q++) s += __ldcg(&g_sumpB[q * 32 + lane]);
        g = MMASS / warp_sum(s);
    }
    const float ab = 1.0f / (float)BN;
    float rowA = 1.f, rowU = 1.f, colB = 1.f, colV = 1.f;

    #pragma unroll 1
    for (int it = 0; it < NITER; it++) {
        // ===== row phase: publish yp partials ================================
        {
            float y1 = 0.f, y2 = 0.f;
            #pragma unroll
            for (int q = 0; q < 16; q++) {
                float b0 = __shfl_sync(0xffffffffu, colB, 2 * q);
                float b1 = __shfl_sync(0xffffffffu, colB, 2 * q + 1);
                float2 kv1 = bf2u(ktp[q]);
                float2 kv2 = bf2u(ktp[16 + q]);
                y1 = fmaf(kv1.x, b0, fmaf(kv1.y, b1, y1));
                y2 = fmaf(kv2.x, b0, fmaf(kv2.y, b1, y2));
            }
            __stcg(&g_yp[b * BN + tid], y1);
            __stcg(&g_yp[b * BN + 512 + tid], y2);
        }
        eph++; bar_arrive(b, tid, eph); bar_wait(lane, eph);

        // ---- deferred mass update + row update (warp-redundant) -------------
        if (it > 0) {
            float s2 = warp_sum(__ldcg(&g_s2p[lane]));
            g *= MMASS / s2;
        }
        {
            float y = 0.f;
            #pragma unroll
            for (int src = 0; src < 32; src++)
                y += __ldcg(&g_yp[src * BN + b * 32 + lane]);
            float r = fminf(ab / (g * rowA * rowU * y), 1.f);
            rowA *= r * rowU;
            rowU = 1.f / r;
        }

        // ===== col phase: publish zp partials ================================
        {
            float z1 = 0.f, z2 = 0.f;
            #pragma unroll
            for (int q = 0; q < 16; q++) {
                float a0 = __shfl_sync(0xffffffffu, rowA, 2 * q);
                float a1 = __shfl_sync(0xffffffffu, rowA, 2 * q + 1);
                float2 kv1 = bf2u(k0p[q]);
                float2 kv2 = bf2u(k0p[16 + q]);
                z1 = fmaf(kv1.x, a0, fmaf(kv1.y, a1, z1));
                z2 = fmaf(kv2.x, a0, fmaf(kv2.y, a1, z2));
            }
            __stcg(&g_zp[b * BN + tid], z1);
            __stcg(&g_zp[b * BN + 512 + tid], z2);
        }
        eph++; bar_arrive(b, tid, eph); bar_wait(lane, eph);

        // ---- col update (warp-redundant) -------------------------------------
        {
            float z = 0.f;
            #pragma unroll
            for (int src = 0; src < 32; src++)
                z += __ldcg(&g_zp[src * BN + b * 32 + lane]);
            float t = g * colV * colB * z;                 // colsum(K1p)
            float c = fminf(ab / t, 1.f);
            colB *= c * colV;
            colV = 1.f / c;
            float s2p = warp_sum(c * t);                   // colsum(K2) partial
            if (w == 0 && lane == 0) __stcg(&g_s2p[b], s2p);
        }
    }

    // ===== finalize: publish beta, last mass update ==========================
    if (w == 0) __stcg(&g_beta[b * 32 + lane], colB);
    eph++; bar_arrive(b, tid, eph); bar_wait(lane, eph);
    {
        float s2 = warp_sum(__ldcg(&g_s2p[lane]));
        g *= MMASS / s2;
    }

    // ===== loss: mean_i( log(1024 + sum_j (exp(pi_ij)-1)) - pi_ii ) =========
    {
        float bet1 = __ldcg(&g_beta[tid]);
        float bet2 = __ldcg(&g_beta[512 + tid]);
        const int bw = b & 15;                    // warp holding block diagonal
        #pragma unroll
        for (int q = 0; q < 16; q++) {
            float a0 = g * __shfl_sync(0xffffffffu, rowA, 2 * q);
            float a1 = g * __shfl_sync(0xffffffffu, rowA, 2 * q + 1);
            float2 kv1 = bf2u(k0p[q]);
            float2 kv2 = bf2u(k0p[16 + q]);
            float x0a = a0 * kv1.x * bet1, x0b = a0 * kv2.x * bet2;  // row 2q
            float x1a = a1 * kv1.y * bet1, x1b = a1 * kv2.y * bet2;  // row 2q+1
            float t0 = x0a * (1.f + x0a * (0.5f + x0a * (1.f / 6.f)))
                     + x0b * (1.f + x0b * (0.5f + x0b * (1.f / 6.f)));
            float t1 = x1a * (1.f + x1a * (0.5f + x1a * (1.f / 6.f)))
                     + x1b * (1.f + x1b * (0.5f + x1b * (1.f / 6.f)));
            t0 = warp_sum(t0);
            t1 = warp_sum(t1);
            if (lane == 0) {
                s_red[(2 * q) * 16 + w]     = t0;
                s_red[(2 * q + 1) * 16 + w] = t1;
            }
            if (w == bw) {        // diagonal pi_ii: j = 32b+r sits in this warp
                if (b < 16) {
                    if (lane == 2 * q)     s_pii[2 * q]     = a0 * kv1.x * bet1;
                    if (lane == 2 * q + 1) s_pii[2 * q + 1] = a1 * kv1.y * bet1;
                } else {
                    if (lane == 2 * q)     s_pii[2 * q]     = a0 * kv2.x * bet2;
                    if (lane == 2 * q + 1) s_pii[2 * q + 1] = a1 * kv2.y * bet2;
                }
            }
        }
    }
    __syncthreads();
    if (w == 0) {
        float acc = 0.f;
        #pragma unroll
        for (int k = 0; k < 16; k++) acc += s_red[lane * 16 + k];
        float lr = logf(1024.f + acc) - s_pii[lane];
        float s = warp_sum(lr);
        if (lane == 0) __stcg(&g_lossp[b], s);
    }
    eph++; bar_arrive(b, tid, eph); bar_wait(lane, eph);

    if (b == 0 && w == 0) {
        float s = warp_sum(__ldcg(&g_lossp[lane]));
        if (lane == 0) out[0] = s * (1.0f / (float)BN);
    }
}

// ===========================================================================
extern "C" void kernel_launch(void* const* d_in, const int* in_sizes, int n_in,
                              void* d_out, int out_size) {
    (void)in_sizes; (void)n_in; (void)out_size;
    const float* A = (const float*)d_in[0];
    const float* T = (const float*)d_in[1];
    float* out = (float*)d_out;

    const int smem_iter = 65536 + (512 + 32) * 4 + 64;   // staging + s_red + s_pii
    cudaFuncSetAttribute(k_iter, cudaFuncAttributeMaxDynamicSharedMemorySize, smem_iter);

    k_convert<<<256, 256>>>(A, T);
    k_gemm<<<128, 256>>>();
    k_build<<<256, 256>>>();
    k_iter<<<NB, NTI, smem_iter>>>(out);
}